// round 15
// baseline (speedup 1.0000x reference)
#include <cuda_runtime.h>
#include <cuda_bf16.h>
#include <cuda_fp16.h>
#include <cstdint>
#include <cstddef>
#include <math.h>

#define D_MODEL 1024
#define N_HEADS 16
#define DKH     64
#define D_FF    4096
#define BB      2
#define TT      2048
#define MROWS   (BB * TT)   // 4096

__device__ float  g_Q   [MROWS * D_MODEL];
__device__ float  g_K   [MROWS * D_MODEL];
__device__ float  g_V   [MROWS * D_MODEL];
__device__ float  g_attn[MROWS * D_MODEL];
__device__ float  g_x1  [MROWS * D_MODEL];
__device__ float  g_x2  [MROWS * D_MODEL];
__device__ float  g_tmp [MROWS * D_MODEL];
__device__ float  g_ffn [MROWS * D_FF];
__device__ float  g_Wt  [D_FF * D_MODEL];          // holds Xh (fp16) + spare
__device__ __half g_wh  [16 * 1024 * 1024];        // 32MB: all transposed weights

// ======================= helpers ============================================
__device__ __forceinline__ uint32_t h2_as_u32(__half2 h) {
    union { __half2 h; uint32_t u; } cvt;
    cvt.h = h;
    return cvt.u;
}

__device__ __forceinline__ void cpa16(uint32_t dst, const void* src) {
    asm volatile("cp.async.cg.shared.global [%0], [%1], 16;\n"
                 :: "r"(dst), "l"(src) : "memory");
}
#define CP_COMMIT() asm volatile("cp.async.commit_group;\n" ::: "memory")
#define CP_WAIT(n)  asm volatile("cp.async.wait_group %0;\n" :: "n"(n) : "memory")

__device__ __forceinline__ uint32_t smem_u32(const void* p) {
    uint32_t a;
    asm("{ .reg .u64 t; cvta.to.shared.u64 t, %1; cvt.u32.u64 %0, t; }"
        : "=r"(a) : "l"(p));
    return a;
}

__device__ __forceinline__ void mma16h(float* c, uint32_t a0, uint32_t a1,
                                       uint32_t a2, uint32_t a3,
                                       uint32_t b0, uint32_t b1) {
    asm volatile(
        "mma.sync.aligned.m16n8k16.row.col.f32.f16.f16.f32 "
        "{%0,%1,%2,%3}, {%4,%5,%6,%7}, {%8,%9}, {%0,%1,%2,%3};"
        : "+f"(c[0]), "+f"(c[1]), "+f"(c[2]), "+f"(c[3])
        : "r"(a0), "r"(a1), "r"(a2), "r"(a3), "r"(b0), "r"(b1));
}

__device__ __forceinline__ void lsm4(uint32_t* r, uint32_t addr) {
    asm volatile("ldmatrix.sync.aligned.m8n8.x4.shared.b16 {%0,%1,%2,%3}, [%4];"
                 : "=r"(r[0]), "=r"(r[1]), "=r"(r[2]), "=r"(r[3]) : "r"(addr));
}

// =============== fp16 mma GEMM: C = A[M,K] @ Wt^T + bias ====================
// Block tile 128x128, 256 thr (8 warps, warp tile 32x64), BK = 64 halves.
// Row stride 144B (conflict-free per ldmatrix phase). 3-stage cp.async.
// 110.6KB smem + <=128 regs -> 2 CTAs/SM.
#define G_ROWB   144
#define G_STAGEB (256 * G_ROWB)            // 36864
#define G_BOFF   (128 * G_ROWB)            // 18432
#define G_NSTG   3
#define G_SMEM   (G_NSTG * G_STAGEB)       // 110592

__global__ __launch_bounds__(256, 2)
void gemm_h(int M, int N, int K,
            const __half* __restrict__ A, const __half* __restrict__ Wt,
            const float* __restrict__ bias, void* __restrict__ C,
            int relu, int outHalf)
{
    extern __shared__ char smc[];
    const uint32_t sb = smem_u32(smc);

    const int tid = threadIdx.x;
    const int wid = tid >> 5, lid = tid & 31;
    const int g = lid >> 2, tg = lid & 3;
    const int wm = wid >> 1, wn = wid & 1;

    const int bRow = blockIdx.y * 128, bCol = blockIdx.x * 128;
    const int NT = K >> 6;

    float acc[2][8][4];
#pragma unroll
    for (int m = 0; m < 2; m++)
#pragma unroll
        for (int n = 0; n < 8; n++)
#pragma unroll
            for (int x = 0; x < 4; x++) acc[m][n][x] = 0.f;

    auto load_stage = [&](int it, int s) {
        const uint32_t base = sb + s * G_STAGEB;
#pragma unroll
        for (int j = 0; j < 4; j++) {
            const int idx = tid + 256 * j;
            const int row = idx >> 3, c16 = idx & 7;
            cpa16(base + row * G_ROWB + c16 * 16,
                  A + (size_t)(bRow + row) * K + it * 64 + c16 * 8);
        }
#pragma unroll
        for (int j = 0; j < 4; j++) {
            const int idx = tid + 256 * j;
            const int row = idx >> 3, c16 = idx & 7;
            cpa16(base + G_BOFF + row * G_ROWB + c16 * 16,
                  Wt + (size_t)(bCol + row) * K + it * 64 + c16 * 8);
        }
    };

    const uint32_t aoff = (uint32_t)((wm * 32 + (lid & 7) + ((lid >> 3) & 1) * 8) * G_ROWB
                                     + (lid >> 4) * 16);
    const uint32_t boff = (uint32_t)(G_BOFF
                                     + (wn * 64 + (lid & 7) + (lid >> 4) * 8) * G_ROWB
                                     + ((lid >> 3) & 1) * 16);

    load_stage(0, 0); CP_COMMIT();
    load_stage(1, 1); CP_COMMIT();

    for (int i = 0; i < NT; i++) {
        CP_WAIT(1);
        __syncthreads();
        const int pre = i + 2;
        if (pre < NT) load_stage(pre, pre % G_NSTG);
        CP_COMMIT();

        const uint32_t buf = sb + (i % G_NSTG) * G_STAGEB;
#pragma unroll
        for (int ks = 0; ks < 4; ks++) {
            uint32_t a[2][4];
#pragma unroll
            for (int mt = 0; mt < 2; mt++)
                lsm4(a[mt], buf + aoff + mt * 16 * G_ROWB + ks * 32);
#pragma unroll
            for (int p = 0; p < 4; p++) {
                uint32_t b[4];
                lsm4(b, buf + boff + p * 16 * G_ROWB + ks * 32);
#pragma unroll
                for (int mt = 0; mt < 2; mt++) {
                    mma16h(acc[mt][2 * p],     a[mt][0], a[mt][1], a[mt][2],
                           a[mt][3], b[0], b[1]);
                    mma16h(acc[mt][2 * p + 1], a[mt][0], a[mt][1], a[mt][2],
                           a[mt][3], b[2], b[3]);
                }
            }
        }
    }

    float* Cf = (float*)C;
    __half* Ch = (__half*)C;
#pragma unroll
    for (int mt = 0; mt < 2; mt++) {
        const int r0 = bRow + wm * 32 + mt * 16 + g;
#pragma unroll
        for (int nt = 0; nt < 8; nt++) {
            const int col = bCol + wn * 64 + nt * 8 + 2 * tg;
            const float bi0 = bias[col], bi1 = bias[col + 1];
            float v0 = acc[mt][nt][0] + bi0, v1 = acc[mt][nt][1] + bi1;
            float v2 = acc[mt][nt][2] + bi0, v3 = acc[mt][nt][3] + bi1;
            if (relu) {
                v0 = fmaxf(v0, 0.f); v1 = fmaxf(v1, 0.f);
                v2 = fmaxf(v2, 0.f); v3 = fmaxf(v3, 0.f);
            }
            if (outHalf) {
                *(__half2*)(Ch + (size_t)r0 * N + col) = __floats2half2_rn(v0, v1);
                *(__half2*)(Ch + (size_t)(r0 + 8) * N + col) = __floats2half2_rn(v2, v3);
            } else {
                *(float2*)(Cf + (size_t)r0 * N + col) = make_float2(v0, v1);
                *(float2*)(Cf + (size_t)(r0 + 8) * N + col) = make_float2(v2, v3);
            }
        }
    }
}

// ---------------- fused weight prep (all transposes, one launch) ------------
struct PrepJob { const float* src; __half* dst; int K, R, isHead, blk0; };
struct PrepArgs { PrepJob j[12]; };

__global__ __launch_bounds__(256) void prep_weights(PrepArgs pa)
{
    __shared__ float t[32][33];
    int ji = 0;
#pragma unroll
    for (int q = 1; q < 12; q++)
        if ((int)blockIdx.x >= pa.j[q].blk0) ji = q;
    const PrepJob& J = pa.j[ji];
    const int b = blockIdx.x - J.blk0;
    const int kt = J.K >> 5;
    const int kx = b % kt, rx = b / kt;
    const int k0 = kx * 32, r0 = rx * 32;
    const int x = threadIdx.x & 31, y = threadIdx.x >> 5;

    if (J.isHead) {
#pragma unroll
        for (int jj = 0; jj < 32; jj += 8) {
            const int n = r0 + x;
            const int hh = n >> 6, d = n & 63;
            t[y + jj][x] = J.src[((size_t)hh * J.K + (k0 + y + jj)) * 64 + d];
        }
    } else {
#pragma unroll
        for (int jj = 0; jj < 32; jj += 8)
            t[y + jj][x] = J.src[(size_t)(k0 + y + jj) * J.R + r0 + x];
    }
    __syncthreads();
#pragma unroll
    for (int jj = 0; jj < 32; jj += 8)
        J.dst[(size_t)(r0 + y + jj) * J.K + k0 + x] = __float2half_rn(t[x][y + jj]);
}

// ---------------- small utils ----------------------------------------------
__global__ __launch_bounds__(256) void h_copy(
    const float* __restrict__ in, __half* __restrict__ out, int n4)
{
    const int i = blockIdx.x * blockDim.x + threadIdx.x;
    if (i < n4) {
        float4 v = ((const float4*)in)[i];
        uint2 o;
        o.x = h2_as_u32(__floats2half2_rn(v.x, v.y));
        o.y = h2_as_u32(__floats2half2_rn(v.z, v.w));
        ((uint2*)out)[i] = o;
    }
}

__global__ void prep_bias(const float* a, const float* b, const float* c,
                          const float* d, const float* e,
                          float* o3, float* o2)
{
    const int i = blockIdx.x * blockDim.x + threadIdx.x;
    if (i < 1024) o3[i] = a[i];
    else if (i < 2048) o3[i] = b[i - 1024];
    else if (i < 3072) o3[i] = c[i - 2048];
    else if (i < 4096) o2[i - 3072] = d[i - 3072];
    else if (i < 5120) o2[i - 3072] = e[i - 4096];
}

// ========== flash attention: 128-query blocks, 256 thr, fp16 mma ============
// K/V tiles register-prefetched one tile ahead (global latency hidden).
// Causal launches heavy q-blocks first (reversed block order).
#define AROW 36   // b32 words per smem row (72 halves)

template<bool CAUSAL>
__global__ __launch_bounds__(256) void attn_mma(
    const __half* __restrict__ Q, const __half* __restrict__ K,
    const __half* __restrict__ V, __half* __restrict__ O,
    int T, int ldq, int ldkv)
{
    __shared__ __align__(16) __half Qs[128 * 72];
    __shared__ __align__(16) __half Ks[64 * 72];
    __shared__ __align__(16) __half Vt[64 * 72];

    const int tid = threadIdx.x, wid = tid >> 5, lid = tid & 31;
    const int g = lid >> 2, tg = lid & 3;
    const int h = blockIdx.y, b = blockIdx.z;
    const int bx = CAUSAL ? (gridDim.x - 1 - blockIdx.x) : blockIdx.x;
    const int q0 = bx * 128;
    const size_t qbase  = (size_t)b * T * ldq  + h * DKH;
    const size_t kvbase = (size_t)b * T * ldkv + h * DKH;
    const size_t obase  = (size_t)b * T * D_MODEL + h * DKH;

    // per-thread tile-fetch indices (each thread owns 2 rows' chunks)
    const int fr0 = tid >> 3, fc = (tid & 7) * 8;      // row, col(halves)
    const int fr1 = fr0 + 32;

    for (int idx = tid; idx < 128 * 8; idx += 256) {
        const int r = idx >> 3, c8 = idx & 7;
        *(uint4*)&Qs[r * 72 + c8 * 8] =
            *(const uint4*)(Q + qbase + (size_t)(q0 + r) * ldq + c8 * 8);
    }
    __syncthreads();

    uint32_t qf[4][4];
    {
        const uint32_t* Qu = (const uint32_t*)Qs;
        const int r0 = wid * 16 + g;
#pragma unroll
        for (int kc = 0; kc < 4; kc++) {
            const int c = 8 * kc + tg;
            qf[kc][0] = Qu[r0 * AROW + c];
            qf[kc][1] = Qu[(r0 + 8) * AROW + c];
            qf[kc][2] = Qu[r0 * AROW + c + 4];
            qf[kc][3] = Qu[(r0 + 8) * AROW + c + 4];
        }
    }

    float oacc[8][4];
#pragma unroll
    for (int j = 0; j < 8; j++)
#pragma unroll
        for (int x = 0; x < 4; x++) oacc[j][x] = 0.f;
    float m0 = -1e30f, m1 = -1e30f, l0 = 0.f, l1 = 0.f;

    const int nkt = CAUSAL ? 2 * (bx + 1) : (T / 64);

    // prologue: fetch tile 0 into registers
    uint4 kreg0, kreg1, vreg0, vreg1;
    {
        const size_t a0 = kvbase + (size_t)fr0 * ldkv + fc;
        const size_t a1 = kvbase + (size_t)fr1 * ldkv + fc;
        kreg0 = *(const uint4*)(K + a0); vreg0 = *(const uint4*)(V + a0);
        kreg1 = *(const uint4*)(K + a1); vreg1 = *(const uint4*)(V + a1);
    }

    for (int kt = 0; kt < nkt; kt++) {
        const int s0 = kt * 64;
        __syncthreads();            // previous compute done; safe to overwrite
        // store prefetched tile to smem (K rows + V transposed)
        *(uint4*)&Ks[fr0 * 72 + fc] = kreg0;
        *(uint4*)&Ks[fr1 * 72 + fc] = kreg1;
        {
            const __half* hv = (const __half*)&vreg0;
#pragma unroll
            for (int q = 0; q < 8; q++) Vt[(fc + q) * 72 + fr0] = hv[q];
            hv = (const __half*)&vreg1;
#pragma unroll
            for (int q = 0; q < 8; q++) Vt[(fc + q) * 72 + fr1] = hv[q];
        }
        // fetch next tile while computing this one
        if (kt + 1 < nkt) {
            const size_t a0 = kvbase + (size_t)(s0 + 64 + fr0) * ldkv + fc;
            const size_t a1 = kvbase + (size_t)(s0 + 64 + fr1) * ldkv + fc;
            kreg0 = *(const uint4*)(K + a0); vreg0 = *(const uint4*)(V + a0);
            kreg1 = *(const uint4*)(K + a1); vreg1 = *(const uint4*)(V + a1);
        }
        __syncthreads();

        if (CAUSAL && s0 >= q0 + wid * 16 + 16) continue;

        float sacc[8][4];
#pragma unroll
        for (int j = 0; j < 8; j++)
#pragma unroll
            for (int x = 0; x < 4; x++) sacc[j][x] = 0.f;
        {
            const uint32_t* Ku = (const uint32_t*)Ks;
#pragma unroll
            for (int j = 0; j < 8; j++) {
                const int rb = (8 * j + g) * AROW + tg;
#pragma unroll
                for (int kc = 0; kc < 4; kc++) {
                    const uint32_t b0 = Ku[rb + 8 * kc];
                    const uint32_t b1 = Ku[rb + 8 * kc + 4];
                    mma16h(sacc[j], qf[kc][0], qf[kc][1], qf[kc][2], qf[kc][3],
                           b0, b1);
                }
            }
        }
#pragma unroll
        for (int j = 0; j < 8; j++) {
            sacc[j][0] *= 0.125f; sacc[j][1] *= 0.125f;
            sacc[j][2] *= 0.125f; sacc[j][3] *= 0.125f;
        }

        if (CAUSAL && s0 + 63 >= q0 + wid * 16) {
            const int r0 = q0 + wid * 16 + g, r1 = r0 + 8;
#pragma unroll
            for (int j = 0; j < 8; j++) {
                const int c0 = s0 + 8 * j + 2 * tg, c1 = c0 + 1;
                if (c0 > r0) sacc[j][0] = -INFINITY;
                if (c1 > r0) sacc[j][1] = -INFINITY;
                if (c0 > r1) sacc[j][2] = -INFINITY;
                if (c1 > r1) sacc[j][3] = -INFINITY;
            }
        }

        float tm0 = -1e30f, tm1 = -1e30f;
#pragma unroll
        for (int j = 0; j < 8; j++) {
            tm0 = fmaxf(tm0, fmaxf(sacc[j][0], sacc[j][1]));
            tm1 = fmaxf(tm1, fmaxf(sacc[j][2], sacc[j][3]));
        }
        tm0 = fmaxf(tm0, __shfl_xor_sync(0xffffffffu, tm0, 1));
        tm0 = fmaxf(tm0, __shfl_xor_sync(0xffffffffu, tm0, 2));
        tm1 = fmaxf(tm1, __shfl_xor_sync(0xffffffffu, tm1, 1));
        tm1 = fmaxf(tm1, __shfl_xor_sync(0xffffffffu, tm1, 2));

        const float mn0 = fmaxf(m0, tm0), mn1 = fmaxf(m1, tm1);
        const float cr0 = __expf(m0 - mn0), cr1 = __expf(m1 - mn1);
        m0 = mn0; m1 = mn1;

        uint32_t ph[8][2];
        float ts0 = 0.f, ts1 = 0.f;
#pragma unroll
        for (int j = 0; j < 8; j++) {
            const float p0 = __expf(sacc[j][0] - mn0);
            const float p1 = __expf(sacc[j][1] - mn0);
            const float p2 = __expf(sacc[j][2] - mn1);
            const float p3 = __expf(sacc[j][3] - mn1);
            ts0 += p0 + p1; ts1 += p2 + p3;
            ph[j][0] = h2_as_u32(__floats2half2_rn(p0, p1));
            ph[j][1] = h2_as_u32(__floats2half2_rn(p2, p3));
        }
        ts0 += __shfl_xor_sync(0xffffffffu, ts0, 1);
        ts0 += __shfl_xor_sync(0xffffffffu, ts0, 2);
        ts1 += __shfl_xor_sync(0xffffffffu, ts1, 1);
        ts1 += __shfl_xor_sync(0xffffffffu, ts1, 2);
        l0 = l0 * cr0 + ts0;
        l1 = l1 * cr1 + ts1;

#pragma unroll
        for (int j = 0; j < 8; j++) {
            oacc[j][0] *= cr0; oacc[j][1] *= cr0;
            oacc[j][2] *= cr1; oacc[j][3] *= cr1;
        }

        {
            const uint32_t* Vu = (const uint32_t*)Vt;
#pragma unroll
            for (int j = 0; j < 8; j++) {
                const int rb = (8 * j + g) * AROW + tg;
#pragma unroll
                for (int kc = 0; kc < 4; kc++) {
                    const uint32_t b0 = Vu[rb + 8 * kc];
                    const uint32_t b1 = Vu[rb + 8 * kc + 4];
                    mma16h(oacc[j], ph[2 * kc][0], ph[2 * kc][1],
                           ph[2 * kc + 1][0], ph[2 * kc + 1][1], b0, b1);
                }
            }
        }
    }

    const float inv0 = 1.f / l0, inv1 = 1.f / l1;
    const int r0 = q0 + wid * 16 + g;
#pragma unroll
    for (int j = 0; j < 8; j++) {
        const int col = 8 * j + 2 * tg;
        *(__half2*)(O + obase + (size_t)r0 * D_MODEL + col) =
            __floats2half2_rn(oacc[j][0] * inv0, oacc[j][1] * inv0);
        *(__half2*)(O + obase + (size_t)(r0 + 8) * D_MODEL + col) =
            __floats2half2_rn(oacc[j][2] * inv1, oacc[j][3] * inv1);
    }
}

// ---------------- residual add + LayerNorm ----------------------------------
__inline__ __device__ float warpSum(float v) {
#pragma unroll
    for (int o = 16; o > 0; o >>= 1) v += __shfl_xor_sync(0xffffffffu, v, o);
    return v;
}

__global__ __launch_bounds__(256) void add_ln_kernel(
    const float* __restrict__ res, const float* __restrict__ y,
    const float* __restrict__ gamma, const float* __restrict__ beta,
    float* __restrict__ out, __half* __restrict__ outh)
{
    const int row = blockIdx.x;
    const int i = threadIdx.x;
    const float4 a  = ((const float4*)(res + (size_t)row * D_MODEL))[i];
    const float4 b4 = ((const float4*)(y   + (size_t)row * D_MODEL))[i];
    const float x0 = a.x + b4.x, x1 = a.y + b4.y, x2 = a.z + b4.z, x3 = a.w + b4.w;

    float s  = x0 + x1 + x2 + x3;
    float sq = x0 * x0 + x1 * x1 + x2 * x2 + x3 * x3;
    s = warpSum(s); sq = warpSum(sq);

    __shared__ float sh[2][8];
    const int w = threadIdx.x >> 5, l = threadIdx.x & 31;
    if (l == 0) { sh[0][w] = s; sh[1][w] = sq; }
    __syncthreads();
    if (threadIdx.x < 32) {
        float aa = (l < 8) ? sh[0][l] : 0.f;
        float bb = (l < 8) ? sh[1][l] : 0.f;
        aa = warpSum(aa); bb = warpSum(bb);
        if (l == 0) { sh[0][0] = aa; sh[1][0] = bb; }
    }
    __syncthreads();
    const float mean = sh[0][0] * (1.f / D_MODEL);
    const float var  = sh[1][0] * (1.f / D_MODEL) - mean * mean;
    const float rinv = rsqrtf(var + 1e-5f);

    const float4 gm = ((const float4*)gamma)[i];
    const float4 be = ((const float4*)beta)[i];
    float4 o;
    o.x = (x0 - mean) * rinv * gm.x + be.x;
    o.y = (x1 - mean) * rinv * gm.y + be.y;
    o.z = (x2 - mean) * rinv * gm.z + be.z;
    o.w = (x3 - mean) * rinv * gm.w + be.w;
    ((float4*)(out + (size_t)row * D_MODEL))[i] = o;
    if (outh) {
        uint2 oh;
        oh.x = h2_as_u32(__floats2half2_rn(o.x, o.y));
        oh.y = h2_as_u32(__floats2half2_rn(o.z, o.w));
        ((uint2*)(outh + (size_t)row * D_MODEL))[i] = oh;
    }
}

// ---------------- launch ----------------------------------------------------
extern "C" void kernel_launch(void* const* d_in, const int* in_sizes, int n_in,
                              void* d_out, int out_size)
{
    const float* dec  = (const float*)d_in[0];
    const float* enc  = (const float*)d_in[1];
    const float* Wq_s = (const float*)d_in[2];
    const float* bq_s = (const float*)d_in[3];
    const float* Wk_s = (const float*)d_in[4];
    const float* bk_s = (const float*)d_in[5];
    const float* Wv_s = (const float*)d_in[6];
    const float* bv_s = (const float*)d_in[7];
    const float* Wo_s = (const float*)d_in[8];
    const float* bo_s = (const float*)d_in[9];
    const float* Wq_c = (const float*)d_in[10];
    const float* bq_c = (const float*)d_in[11];
    const float* Wk_c = (const float*)d_in[12];
    const float* bk_c = (const float*)d_in[13];
    const float* Wv_c = (const float*)d_in[14];
    const float* bv_c = (const float*)d_in[15];
    const float* Wo_c = (const float*)d_in[16];
    const float* bo_c = (const float*)d_in[17];
    const float* W1   = (const float*)d_in[18];
    const float* b1   = (const float*)d_in[19];
    const float* W2   = (const float*)d_in[20];
    const float* b2   = (const float*)d_in[21];
    const float* g1   = (const float*)d_in[22];
    const float* be1  = (const float*)d_in[23];
    const float* g2   = (const float*)d_in[24];
    const float* be2  = (const float*)d_in[25];
    const float* g3   = (const float*)d_in[26];
    const float* be3  = (const float*)d_in[27];

    float *Qf, *Kf, *Vf, *Af, *X1, *X2, *Tm, *Fbuf, *Wtb;
    __half* Wh;
    cudaGetSymbolAddress((void**)&Qf, g_Q);
    cudaGetSymbolAddress((void**)&Kf, g_K);
    cudaGetSymbolAddress((void**)&Vf, g_V);
    cudaGetSymbolAddress((void**)&Af, g_attn);
    cudaGetSymbolAddress((void**)&X1, g_x1);
    cudaGetSymbolAddress((void**)&X2, g_x2);
    cudaGetSymbolAddress((void**)&Tm, g_tmp);
    cudaGetSymbolAddress((void**)&Fbuf, g_ffn);
    cudaGetSymbolAddress((void**)&Wtb, g_Wt);
    cudaGetSymbolAddress((void**)&Wh, g_wh);

    const size_t NE = (size_t)MROWS * D_MODEL;        // 4M
    const size_t MM = (size_t)D_MODEL * D_MODEL;      // 1M
    __half* dec_h = (__half*)Qf;
    __half* enc_h = dec_h + NE;
    __half* Qhc   = (__half*)Kf;
    __half* KVc   = (__half*)Vf;                      // ld 2048
    __half* Ath   = (__half*)Af;
    float*  biasQ = (float*)(Ath + NE);
    float*  biasK = biasQ + 4096;
    __half* QKV   = (__half*)Fbuf;                    // ld 3072
    __half* Ffh   = QKV + (size_t)MROWS * 3072;
    __half* w_qkv_s = Wh;
    __half* w_o_s   = Wh + 3 * MM;
    __half* w_qkv_c = Wh + 4 * MM;
    __half* w_o_c   = Wh + 7 * MM;
    __half* w_1     = Wh + 8 * MM;
    __half* w_2     = Wh + 12 * MM;
    __half* Xh      = (__half*)Wtb;

    cudaFuncSetAttribute(gemm_h, cudaFuncAttributeMaxDynamicSharedMemorySize, G_SMEM);

    PrepArgs pa;
    auto setj = [&](int i, const float* s, __half* d, int K, int R, int ih, int b0) {
        pa.j[i] = PrepJob{s, d, K, R, ih, b0};
    };
    setj(0,  Wq_s, w_qkv_s,            1024, 1024, 1, 0);
    setj(1,  Wk_s, w_qkv_s + MM,       1024, 1024, 1, 1024);
    setj(2,  Wv_s, w_qkv_s + 2 * MM,   1024, 1024, 1, 2048);
    setj(3,  Wo_s, w_o_s,              1024, 1024, 0, 3072);
    setj(4,  Wq_c, w_qkv_c,            1024, 1024, 1, 4096);
    setj(5,  Wk_c, w_qkv_c + MM,       1024, 1024, 1, 5120);
    setj(6,  Wv_c, w_qkv_c + 2 * MM,   1024, 1024, 1, 6144);
    setj(7,  Wo_c, w_o_c,              1024, 1024, 0, 7168);
    setj(8,  W1,   w_1,                1024, 4096, 0, 8192);
    setj(9,  W2,   w_2,                4096, 1024, 0, 12288);
    setj(10, W2,   w_2,                4096, 1024, 0, 0x7fffffff);
    setj(11, W2,   w_2,                4096, 1024, 0, 0x7fffffff);

    const dim3 gD (D_MODEL / 128, MROWS / 128);        // (8, 32)
    const dim3 gD3(3 * D_MODEL / 128, MROWS / 128);    // (24, 32)
    const dim3 gD2(2 * D_MODEL / 128, MROWS / 128);    // (16, 32)
    const dim3 gF (D_FF / 128,   MROWS / 128);         // (32, 32)
    const dim3 gA(TT / 128, N_HEADS, BB);
    const int NC4 = MROWS * D_MODEL / 4;

    prep_weights<<<16384, 256>>>(pa);
    h_copy<<<(NC4 + 255) / 256, 256>>>(dec, dec_h, NC4);
    h_copy<<<(NC4 + 255) / 256, 256>>>(enc, enc_h, NC4);
    prep_bias<<<20, 256>>>(bq_s, bk_s, bv_s, bk_c, bv_c, biasQ, biasK);

    // ---- self-attention block ----
    gemm_h<<<gD3, 256, G_SMEM>>>(MROWS, 3 * D_MODEL, D_MODEL, dec_h, w_qkv_s, biasQ, QKV, 0, 1);
    attn_mma<true><<<gA, 256>>>(QKV, QKV + 1024, QKV + 2048, Ath, TT, 3072, 3072);
    gemm_h<<<gD, 256, G_SMEM>>>(MROWS, D_MODEL, D_MODEL, Ath, w_o_s, bo_s, Tm, 0, 0);
    add_ln_kernel<<<MROWS, 256>>>(dec, Tm, g1, be1, X1, Xh);

    // ---- cross-attention block ----
    gemm_h<<<gD, 256, G_SMEM>>>(MROWS, D_MODEL, D_MODEL, Xh, w_qkv_c, bq_c, Qhc, 0, 1);
    gemm_h<<<gD2, 256, G_SMEM>>>(MROWS, 2 * D_MODEL, D_MODEL, enc_h,
                                 w_qkv_c + MM, biasK, KVc, 0, 1);
    attn_mma<false><<<gA, 256>>>(Qhc, KVc, KVc + 1024, Ath, TT, 1024, 2048);
    gemm_h<<<gD, 256, G_SMEM>>>(MROWS, D_MODEL, D_MODEL, Ath, w_o_c, bo_c, Tm, 0, 0);
    add_ln_kernel<<<MROWS, 256>>>(X1, Tm, g2, be2, X2, Xh);

    // ---- FFN block ----
    gemm_h<<<gF, 256, G_SMEM>>>(MROWS, D_FF, D_MODEL, Xh, w_1, b1, Ffh, 1, 1);
    gemm_h<<<gD, 256, G_SMEM>>>(MROWS, D_MODEL, D_FF, Ffh, w_2, b2, Tm, 0, 0);
    add_ln_kernel<<<MROWS, 256>>>(X2, Tm, g3, be3, (float*)d_out, (__half*)nullptr);
}

// round 16
// speedup vs baseline: 1.0098x; 1.0098x over previous
#include <cuda_runtime.h>
#include <cuda_bf16.h>
#include <cuda_fp16.h>
#include <cstdint>
#include <cstddef>
#include <math.h>

#define D_MODEL 1024
#define N_HEADS 16
#define DKH     64
#define D_FF    4096
#define BB      2
#define TT      2048
#define MROWS   (BB * TT)   // 4096

__device__ float  g_Q   [MROWS * D_MODEL];
__device__ float  g_K   [MROWS * D_MODEL];
__device__ float  g_V   [MROWS * D_MODEL];
__device__ float  g_attn[MROWS * D_MODEL];
__device__ float  g_x1  [MROWS * D_MODEL];
__device__ float  g_x2  [MROWS * D_MODEL];
__device__ float  g_tmp [MROWS * D_MODEL];
__device__ float  g_ffn [MROWS * D_FF];
__device__ float  g_Wt  [D_FF * D_MODEL];          // holds Xh (fp16) + spare
__device__ __half g_wh  [16 * 1024 * 1024];        // 32MB: all transposed weights

// ======================= helpers ============================================
__device__ __forceinline__ uint32_t h2_as_u32(__half2 h) {
    union { __half2 h; uint32_t u; } cvt;
    cvt.h = h;
    return cvt.u;
}

__device__ __forceinline__ void cpa16(uint32_t dst, const void* src) {
    asm volatile("cp.async.cg.shared.global [%0], [%1], 16;\n"
                 :: "r"(dst), "l"(src) : "memory");
}
#define CP_COMMIT() asm volatile("cp.async.commit_group;\n" ::: "memory")
#define CP_WAIT(n)  asm volatile("cp.async.wait_group %0;\n" :: "n"(n) : "memory")

__device__ __forceinline__ uint32_t smem_u32(const void* p) {
    uint32_t a;
    asm("{ .reg .u64 t; cvta.to.shared.u64 t, %1; cvt.u32.u64 %0, t; }"
        : "=r"(a) : "l"(p));
    return a;
}

__device__ __forceinline__ void mma16h(float* c, uint32_t a0, uint32_t a1,
                                       uint32_t a2, uint32_t a3,
                                       uint32_t b0, uint32_t b1) {
    asm volatile(
        "mma.sync.aligned.m16n8k16.row.col.f32.f16.f16.f32 "
        "{%0,%1,%2,%3}, {%4,%5,%6,%7}, {%8,%9}, {%0,%1,%2,%3};"
        : "+f"(c[0]), "+f"(c[1]), "+f"(c[2]), "+f"(c[3])
        : "r"(a0), "r"(a1), "r"(a2), "r"(a3), "r"(b0), "r"(b1));
}

__device__ __forceinline__ void lsm4(uint32_t* r, uint32_t addr) {
    asm volatile("ldmatrix.sync.aligned.m8n8.x4.shared.b16 {%0,%1,%2,%3}, [%4];"
                 : "=r"(r[0]), "=r"(r[1]), "=r"(r[2]), "=r"(r[3]) : "r"(addr));
}

// =============== fp16 mma GEMM: C = A[M,K] @ Wt^T + bias ====================
// Block tile 128x128, 256 thr (8 warps, warp tile 32x64), BK = 64 halves.
// Optional column split: CTAs with bCol >= split read A2 and write C2 (ld2).
#define G_ROWB   144
#define G_STAGEB (256 * G_ROWB)            // 36864
#define G_BOFF   (128 * G_ROWB)            // 18432
#define G_NSTG   3
#define G_SMEM   (G_NSTG * G_STAGEB)       // 110592

__global__ __launch_bounds__(256, 2)
void gemm_h(int M, int N, int K,
            const __half* __restrict__ A, const __half* __restrict__ Wt,
            const float* __restrict__ bias, void* __restrict__ C,
            int relu, int outHalf,
            const __half* __restrict__ A2, __half* __restrict__ C2,
            int split, int ld2)
{
    extern __shared__ char smc[];
    const uint32_t sb = smem_u32(smc);

    const int tid = threadIdx.x;
    const int wid = tid >> 5, lid = tid & 31;
    const int g = lid >> 2, tg = lid & 3;
    const int wm = wid >> 1, wn = wid & 1;

    const int bRow = blockIdx.y * 128, bCol = blockIdx.x * 128;
    const int NT = K >> 6;
    const bool reg2 = (split != 0) && (bCol >= split);
    const __half* Asel = reg2 ? A2 : A;

    float acc[2][8][4];
#pragma unroll
    for (int m = 0; m < 2; m++)
#pragma unroll
        for (int n = 0; n < 8; n++)
#pragma unroll
            for (int x = 0; x < 4; x++) acc[m][n][x] = 0.f;

    auto load_stage = [&](int it, int s) {
        const uint32_t base = sb + s * G_STAGEB;
#pragma unroll
        for (int j = 0; j < 4; j++) {
            const int idx = tid + 256 * j;
            const int row = idx >> 3, c16 = idx & 7;
            cpa16(base + row * G_ROWB + c16 * 16,
                  Asel + (size_t)(bRow + row) * K + it * 64 + c16 * 8);
        }
#pragma unroll
        for (int j = 0; j < 4; j++) {
            const int idx = tid + 256 * j;
            const int row = idx >> 3, c16 = idx & 7;
            cpa16(base + G_BOFF + row * G_ROWB + c16 * 16,
                  Wt + (size_t)(bCol + row) * K + it * 64 + c16 * 8);
        }
    };

    const uint32_t aoff = (uint32_t)((wm * 32 + (lid & 7) + ((lid >> 3) & 1) * 8) * G_ROWB
                                     + (lid >> 4) * 16);
    const uint32_t boff = (uint32_t)(G_BOFF
                                     + (wn * 64 + (lid & 7) + (lid >> 4) * 8) * G_ROWB
                                     + ((lid >> 3) & 1) * 16);

    load_stage(0, 0); CP_COMMIT();
    load_stage(1, 1); CP_COMMIT();

    for (int i = 0; i < NT; i++) {
        CP_WAIT(1);
        __syncthreads();
        const int pre = i + 2;
        if (pre < NT) load_stage(pre, pre % G_NSTG);
        CP_COMMIT();

        const uint32_t buf = sb + (i % G_NSTG) * G_STAGEB;
#pragma unroll
        for (int ks = 0; ks < 4; ks++) {
            uint32_t a[2][4];
#pragma unroll
            for (int mt = 0; mt < 2; mt++)
                lsm4(a[mt], buf + aoff + mt * 16 * G_ROWB + ks * 32);
#pragma unroll
            for (int p = 0; p < 4; p++) {
                uint32_t b[4];
                lsm4(b, buf + boff + p * 16 * G_ROWB + ks * 32);
#pragma unroll
                for (int mt = 0; mt < 2; mt++) {
                    mma16h(acc[mt][2 * p],     a[mt][0], a[mt][1], a[mt][2],
                           a[mt][3], b[0], b[1]);
                    mma16h(acc[mt][2 * p + 1], a[mt][0], a[mt][1], a[mt][2],
                           a[mt][3], b[2], b[3]);
                }
            }
        }
    }

    float* Cf = (float*)C;
    __half* Ch = reg2 ? C2 : (__half*)C;
    const int ldo = reg2 ? ld2 : N;
    const int cbase = reg2 ? (bCol - split) : bCol;
#pragma unroll
    for (int mt = 0; mt < 2; mt++) {
        const int r0 = bRow + wm * 32 + mt * 16 + g;
#pragma unroll
        for (int nt = 0; nt < 8; nt++) {
            const int gcol = bCol + wn * 64 + nt * 8 + 2 * tg;       // bias index
            const int col  = cbase + wn * 64 + nt * 8 + 2 * tg;      // output index
            const float bi0 = bias[gcol], bi1 = bias[gcol + 1];
            float v0 = acc[mt][nt][0] + bi0, v1 = acc[mt][nt][1] + bi1;
            float v2 = acc[mt][nt][2] + bi0, v3 = acc[mt][nt][3] + bi1;
            if (relu) {
                v0 = fmaxf(v0, 0.f); v1 = fmaxf(v1, 0.f);
                v2 = fmaxf(v2, 0.f); v3 = fmaxf(v3, 0.f);
            }
            if (outHalf || reg2) {
                *(__half2*)(Ch + (size_t)r0 * ldo + col) = __floats2half2_rn(v0, v1);
                *(__half2*)(Ch + (size_t)(r0 + 8) * ldo + col) = __floats2half2_rn(v2, v3);
            } else {
                *(float2*)(Cf + (size_t)r0 * ldo + col) = make_float2(v0, v1);
                *(float2*)(Cf + (size_t)(r0 + 8) * ldo + col) = make_float2(v2, v3);
            }
        }
    }
}

// ---------------- mega prep: weights + activations + biases, ONE launch -----
struct PrepJob { const float* src; __half* dst; int K, R, isHead, blk0; };
struct PrepArgs {
    PrepJob j[10];
    const float *dec, *enc;
    __half *dec_h, *enc_h;
    const float *b0, *b1, *b2, *b3, *b4, *b5;   // bq_s bk_s bv_s bq_c bk_c bv_c
    float *o_self, *o_cross;                    // 3072 each
};

#define PREP_WBLK  16384
#define PREP_DEC   (PREP_WBLK)          // 4096 blocks
#define PREP_ENC   (PREP_DEC + 4096)
#define PREP_BIAS  (PREP_ENC + 4096)    // 24 blocks
#define PREP_TOTAL (PREP_BIAS + 24)

__global__ __launch_bounds__(256) void mega_prep(PrepArgs pa)
{
    __shared__ float t[32][33];
    const int bx = blockIdx.x, tid = threadIdx.x;

    if (bx < PREP_WBLK) {
        int ji = 0;
#pragma unroll
        for (int q = 1; q < 10; q++)
            if (bx >= pa.j[q].blk0) ji = q;
        const PrepJob& J = pa.j[ji];
        const int b = bx - J.blk0;
        const int kt = J.K >> 5;
        const int kx = b % kt, rx = b / kt;
        const int k0 = kx * 32, r0 = rx * 32;
        const int x = tid & 31, y = tid >> 5;

        if (J.isHead) {
#pragma unroll
            for (int jj = 0; jj < 32; jj += 8) {
                const int n = r0 + x;
                const int hh = n >> 6, d = n & 63;
                t[y + jj][x] = J.src[((size_t)hh * J.K + (k0 + y + jj)) * 64 + d];
            }
        } else {
#pragma unroll
            for (int jj = 0; jj < 32; jj += 8)
                t[y + jj][x] = J.src[(size_t)(k0 + y + jj) * J.R + r0 + x];
        }
        __syncthreads();
#pragma unroll
        for (int jj = 0; jj < 32; jj += 8)
            J.dst[(size_t)(r0 + y + jj) * J.K + k0 + x] = __float2half_rn(t[x][y + jj]);
    } else if (bx < PREP_ENC) {
        const bool isDec = bx < PREP_DEC + 4096 && bx < PREP_ENC && bx < PREP_DEC + 4096;
        const int i = (bx - (bx < PREP_ENC && bx >= PREP_DEC ? PREP_DEC : PREP_ENC)) * 256 + tid;
        // (branch resolved below properly)
        const float* in = (bx < PREP_ENC && bx >= PREP_DEC) ? pa.dec : pa.enc;
        __half* out = (bx < PREP_ENC && bx >= PREP_DEC) ? pa.dec_h : pa.enc_h;
        (void)isDec;
        float4 v = ((const float4*)in)[i];
        uint2 o;
        o.x = h2_as_u32(__floats2half2_rn(v.x, v.y));
        o.y = h2_as_u32(__floats2half2_rn(v.z, v.w));
        ((uint2*)out)[i] = o;
    } else if (bx < PREP_BIAS) {
        const int i = (bx - PREP_ENC) * 256 + tid;
        float4 v = ((const float4*)pa.enc)[i];
        uint2 o;
        o.x = h2_as_u32(__floats2half2_rn(v.x, v.y));
        o.y = h2_as_u32(__floats2half2_rn(v.z, v.w));
        ((uint2*)pa.enc_h)[i] = o;
    } else {
        const int i = (bx - PREP_BIAS) * 256 + tid;    // 0..6143
        if (i < 1024)      pa.o_self[i] = pa.b0[i];
        else if (i < 2048) pa.o_self[i] = pa.b1[i - 1024];
        else if (i < 3072) pa.o_self[i] = pa.b2[i - 2048];
        else if (i < 4096) pa.o_cross[i - 3072] = pa.b3[i - 3072];
        else if (i < 5120) pa.o_cross[i - 3072] = pa.b4[i - 4096];
        else               pa.o_cross[i - 3072] = pa.b5[i - 5120];
    }
}

// ========== flash attention: 128-query blocks, 256 thr, fp16 mma ============
#define AROW 36   // b32 words per smem row (72 halves)

template<bool CAUSAL>
__global__ __launch_bounds__(256) void attn_mma(
    const __half* __restrict__ Q, const __half* __restrict__ K,
    const __half* __restrict__ V, __half* __restrict__ O,
    int T, int ldq, int ldkv)
{
    __shared__ __align__(16) __half Qs[128 * 72];
    __shared__ __align__(16) __half Ks[64 * 72];
    __shared__ __align__(16) __half Vt[64 * 72];

    const int tid = threadIdx.x, wid = tid >> 5, lid = tid & 31;
    const int g = lid >> 2, tg = lid & 3;
    const int h = blockIdx.y, b = blockIdx.z;
    const int bx = CAUSAL ? (gridDim.x - 1 - blockIdx.x) : blockIdx.x;
    const int q0 = bx * 128;
    const size_t qbase  = (size_t)b * T * ldq  + h * DKH;
    const size_t kvbase = (size_t)b * T * ldkv + h * DKH;
    const size_t obase  = (size_t)b * T * D_MODEL + h * DKH;

    const int fr0 = tid >> 3, fc = (tid & 7) * 8;
    const int fr1 = fr0 + 32;

    for (int idx = tid; idx < 128 * 8; idx += 256) {
        const int r = idx >> 3, c8 = idx & 7;
        *(uint4*)&Qs[r * 72 + c8 * 8] =
            *(const uint4*)(Q + qbase + (size_t)(q0 + r) * ldq + c8 * 8);
    }
    __syncthreads();

    uint32_t qf[4][4];
    {
        const uint32_t* Qu = (const uint32_t*)Qs;
        const int r0 = wid * 16 + g;
#pragma unroll
        for (int kc = 0; kc < 4; kc++) {
            const int c = 8 * kc + tg;
            qf[kc][0] = Qu[r0 * AROW + c];
            qf[kc][1] = Qu[(r0 + 8) * AROW + c];
            qf[kc][2] = Qu[r0 * AROW + c + 4];
            qf[kc][3] = Qu[(r0 + 8) * AROW + c + 4];
        }
    }

    float oacc[8][4];
#pragma unroll
    for (int j = 0; j < 8; j++)
#pragma unroll
        for (int x = 0; x < 4; x++) oacc[j][x] = 0.f;
    float m0 = -1e30f, m1 = -1e30f, l0 = 0.f, l1 = 0.f;

    const int nkt = CAUSAL ? 2 * (bx + 1) : (T / 64);

    uint4 kreg0, kreg1, vreg0, vreg1;
    {
        const size_t a0 = kvbase + (size_t)fr0 * ldkv + fc;
        const size_t a1 = kvbase + (size_t)fr1 * ldkv + fc;
        kreg0 = *(const uint4*)(K + a0); vreg0 = *(const uint4*)(V + a0);
        kreg1 = *(const uint4*)(K + a1); vreg1 = *(const uint4*)(V + a1);
    }

    for (int kt = 0; kt < nkt; kt++) {
        const int s0 = kt * 64;
        __syncthreads();
        *(uint4*)&Ks[fr0 * 72 + fc] = kreg0;
        *(uint4*)&Ks[fr1 * 72 + fc] = kreg1;
        {
            const __half* hv = (const __half*)&vreg0;
#pragma unroll
            for (int q = 0; q < 8; q++) Vt[(fc + q) * 72 + fr0] = hv[q];
            hv = (const __half*)&vreg1;
#pragma unroll
            for (int q = 0; q < 8; q++) Vt[(fc + q) * 72 + fr1] = hv[q];
        }
        if (kt + 1 < nkt) {
            const size_t a0 = kvbase + (size_t)(s0 + 64 + fr0) * ldkv + fc;
            const size_t a1 = kvbase + (size_t)(s0 + 64 + fr1) * ldkv + fc;
            kreg0 = *(const uint4*)(K + a0); vreg0 = *(const uint4*)(V + a0);
            kreg1 = *(const uint4*)(K + a1); vreg1 = *(const uint4*)(V + a1);
        }
        __syncthreads();

        if (CAUSAL && s0 >= q0 + wid * 16 + 16) continue;

        float sacc[8][4];
#pragma unroll
        for (int j = 0; j < 8; j++)
#pragma unroll
            for (int x = 0; x < 4; x++) sacc[j][x] = 0.f;
        {
            const uint32_t* Ku = (const uint32_t*)Ks;
#pragma unroll
            for (int j = 0; j < 8; j++) {
                const int rb = (8 * j + g) * AROW + tg;
#pragma unroll
                for (int kc = 0; kc < 4; kc++) {
                    const uint32_t b0 = Ku[rb + 8 * kc];
                    const uint32_t b1 = Ku[rb + 8 * kc + 4];
                    mma16h(sacc[j], qf[kc][0], qf[kc][1], qf[kc][2], qf[kc][3],
                           b0, b1);
                }
            }
        }
#pragma unroll
        for (int j = 0; j < 8; j++) {
            sacc[j][0] *= 0.125f; sacc[j][1] *= 0.125f;
            sacc[j][2] *= 0.125f; sacc[j][3] *= 0.125f;
        }

        if (CAUSAL && s0 + 63 >= q0 + wid * 16) {
            const int r0 = q0 + wid * 16 + g, r1 = r0 + 8;
#pragma unroll
            for (int j = 0; j < 8; j++) {
                const int c0 = s0 + 8 * j + 2 * tg, c1 = c0 + 1;
                if (c0 > r0) sacc[j][0] = -INFINITY;
                if (c1 > r0) sacc[j][1] = -INFINITY;
                if (c0 > r1) sacc[j][2] = -INFINITY;
                if (c1 > r1) sacc[j][3] = -INFINITY;
            }
        }

        float tm0 = -1e30f, tm1 = -1e30f;
#pragma unroll
        for (int j = 0; j < 8; j++) {
            tm0 = fmaxf(tm0, fmaxf(sacc[j][0], sacc[j][1]));
            tm1 = fmaxf(tm1, fmaxf(sacc[j][2], sacc[j][3]));
        }
        tm0 = fmaxf(tm0, __shfl_xor_sync(0xffffffffu, tm0, 1));
        tm0 = fmaxf(tm0, __shfl_xor_sync(0xffffffffu, tm0, 2));
        tm1 = fmaxf(tm1, __shfl_xor_sync(0xffffffffu, tm1, 1));
        tm1 = fmaxf(tm1, __shfl_xor_sync(0xffffffffu, tm1, 2));

        const float mn0 = fmaxf(m0, tm0), mn1 = fmaxf(m1, tm1);
        const float cr0 = __expf(m0 - mn0), cr1 = __expf(m1 - mn1);
        m0 = mn0; m1 = mn1;

        uint32_t ph[8][2];
        float ts0 = 0.f, ts1 = 0.f;
#pragma unroll
        for (int j = 0; j < 8; j++) {
            const float p0 = __expf(sacc[j][0] - mn0);
            const float p1 = __expf(sacc[j][1] - mn0);
            const float p2 = __expf(sacc[j][2] - mn1);
            const float p3 = __expf(sacc[j][3] - mn1);
            ts0 += p0 + p1; ts1 += p2 + p3;
            ph[j][0] = h2_as_u32(__floats2half2_rn(p0, p1));
            ph[j][1] = h2_as_u32(__floats2half2_rn(p2, p3));
        }
        ts0 += __shfl_xor_sync(0xffffffffu, ts0, 1);
        ts0 += __shfl_xor_sync(0xffffffffu, ts0, 2);
        ts1 += __shfl_xor_sync(0xffffffffu, ts1, 1);
        ts1 += __shfl_xor_sync(0xffffffffu, ts1, 2);
        l0 = l0 * cr0 + ts0;
        l1 = l1 * cr1 + ts1;

#pragma unroll
        for (int j = 0; j < 8; j++) {
            oacc[j][0] *= cr0; oacc[j][1] *= cr0;
            oacc[j][2] *= cr1; oacc[j][3] *= cr1;
        }

        {
            const uint32_t* Vu = (const uint32_t*)Vt;
#pragma unroll
            for (int j = 0; j < 8; j++) {
                const int rb = (8 * j + g) * AROW + tg;
#pragma unroll
                for (int kc = 0; kc < 4; kc++) {
                    const uint32_t b0 = Vu[rb + 8 * kc];
                    const uint32_t b1 = Vu[rb + 8 * kc + 4];
                    mma16h(oacc[j], ph[2 * kc][0], ph[2 * kc][1],
                           ph[2 * kc + 1][0], ph[2 * kc + 1][1], b0, b1);
                }
            }
        }
    }

    const float inv0 = 1.f / l0, inv1 = 1.f / l1;
    const int r0 = q0 + wid * 16 + g;
#pragma unroll
    for (int j = 0; j < 8; j++) {
        const int col = 8 * j + 2 * tg;
        *(__half2*)(O + obase + (size_t)r0 * D_MODEL + col) =
            __floats2half2_rn(oacc[j][0] * inv0, oacc[j][1] * inv0);
        *(__half2*)(O + obase + (size_t)(r0 + 8) * D_MODEL + col) =
            __floats2half2_rn(oacc[j][2] * inv1, oacc[j][3] * inv1);
    }
}

// ---------------- residual add + LayerNorm ----------------------------------
__inline__ __device__ float warpSum(float v) {
#pragma unroll
    for (int o = 16; o > 0; o >>= 1) v += __shfl_xor_sync(0xffffffffu, v, o);
    return v;
}

__global__ __launch_bounds__(256) void add_ln_kernel(
    const float* __restrict__ res, const float* __restrict__ y,
    const float* __restrict__ gamma, const float* __restrict__ beta,
    float* __restrict__ out, __half* __restrict__ outh)
{
    const int row = blockIdx.x;
    const int i = threadIdx.x;
    const float4 a  = ((const float4*)(res + (size_t)row * D_MODEL))[i];
    const float4 b4 = ((const float4*)(y   + (size_t)row * D_MODEL))[i];
    const float x0 = a.x + b4.x, x1 = a.y + b4.y, x2 = a.z + b4.z, x3 = a.w + b4.w;

    float s  = x0 + x1 + x2 + x3;
    float sq = x0 * x0 + x1 * x1 + x2 * x2 + x3 * x3;
    s = warpSum(s); sq = warpSum(sq);

    __shared__ float sh[2][8];
    const int w = threadIdx.x >> 5, l = threadIdx.x & 31;
    if (l == 0) { sh[0][w] = s; sh[1][w] = sq; }
    __syncthreads();
    if (threadIdx.x < 32) {
        float aa = (l < 8) ? sh[0][l] : 0.f;
        float bb = (l < 8) ? sh[1][l] : 0.f;
        aa = warpSum(aa); bb = warpSum(bb);
        if (l == 0) { sh[0][0] = aa; sh[1][0] = bb; }
    }
    __syncthreads();
    const float mean = sh[0][0] * (1.f / D_MODEL);
    const float var  = sh[1][0] * (1.f / D_MODEL) - mean * mean;
    const float rinv = rsqrtf(var + 1e-5f);

    const float4 gm = ((const float4*)gamma)[i];
    const float4 be = ((const float4*)beta)[i];
    float4 o;
    o.x = (x0 - mean) * rinv * gm.x + be.x;
    o.y = (x1 - mean) * rinv * gm.y + be.y;
    o.z = (x2 - mean) * rinv * gm.z + be.z;
    o.w = (x3 - mean) * rinv * gm.w + be.w;
    ((float4*)(out + (size_t)row * D_MODEL))[i] = o;
    if (outh) {
        uint2 oh;
        oh.x = h2_as_u32(__floats2half2_rn(o.x, o.y));
        oh.y = h2_as_u32(__floats2half2_rn(o.z, o.w));
        ((uint2*)(outh + (size_t)row * D_MODEL))[i] = oh;
    }
}

// ---------------- launch ----------------------------------------------------
extern "C" void kernel_launch(void* const* d_in, const int* in_sizes, int n_in,
                              void* d_out, int out_size)
{
    const float* dec  = (const float*)d_in[0];
    const float* enc  = (const float*)d_in[1];
    const float* Wq_s = (const float*)d_in[2];
    const float* bq_s = (const float*)d_in[3];
    const float* Wk_s = (const float*)d_in[4];
    const float* bk_s = (const float*)d_in[5];
    const float* Wv_s = (const float*)d_in[6];
    const float* bv_s = (const float*)d_in[7];
    const float* Wo_s = (const float*)d_in[8];
    const float* bo_s = (const float*)d_in[9];
    const float* Wq_c = (const float*)d_in[10];
    const float* bq_c = (const float*)d_in[11];
    const float* Wk_c = (const float*)d_in[12];
    const float* bk_c = (const float*)d_in[13];
    const float* Wv_c = (const float*)d_in[14];
    const float* bv_c = (const float*)d_in[15];
    const float* Wo_c = (const float*)d_in[16];
    const float* bo_c = (const float*)d_in[17];
    const float* W1   = (const float*)d_in[18];
    const float* b1   = (const float*)d_in[19];
    const float* W2   = (const float*)d_in[20];
    const float* b2   = (const float*)d_in[21];
    const float* g1   = (const float*)d_in[22];
    const float* be1  = (const float*)d_in[23];
    const float* g2   = (const float*)d_in[24];
    const float* be2  = (const float*)d_in[25];
    const float* g3   = (const float*)d_in[26];
    const float* be3  = (const float*)d_in[27];

    float *Qf, *Kf, *Vf, *Af, *X1, *X2, *Tm, *Fbuf, *Wtb;
    __half* Wh;
    cudaGetSymbolAddress((void**)&Qf, g_Q);
    cudaGetSymbolAddress((void**)&Kf, g_K);
    cudaGetSymbolAddress((void**)&Vf, g_V);
    cudaGetSymbolAddress((void**)&Af, g_attn);
    cudaGetSymbolAddress((void**)&X1, g_x1);
    cudaGetSymbolAddress((void**)&X2, g_x2);
    cudaGetSymbolAddress((void**)&Tm, g_tmp);
    cudaGetSymbolAddress((void**)&Fbuf, g_ffn);
    cudaGetSymbolAddress((void**)&Wtb, g_Wt);
    cudaGetSymbolAddress((void**)&Wh, g_wh);

    const size_t NE = (size_t)MROWS * D_MODEL;        // 4M
    const size_t MM = (size_t)D_MODEL * D_MODEL;      // 1M
    __half* dec_h = (__half*)Qf;
    __half* enc_h = dec_h + NE;
    __half* Qhc   = (__half*)Kf;
    __half* KVc   = (__half*)Vf;                      // ld 2048
    __half* Ath   = (__half*)Af;
    float*  biasQ = (float*)(Ath + NE);               // self 3072
    float*  biasC = biasQ + 4096;                     // cross 3072
    __half* QKV   = (__half*)Fbuf;                    // ld 3072
    __half* Ffh   = QKV + (size_t)MROWS * 3072;
    __half* w_qkv_s = Wh;
    __half* w_o_s   = Wh + 3 * MM;
    __half* w_qkv_c = Wh + 4 * MM;
    __half* w_o_c   = Wh + 7 * MM;
    __half* w_1     = Wh + 8 * MM;
    __half* w_2     = Wh + 12 * MM;
    __half* Xh      = (__half*)Wtb;

    cudaFuncSetAttribute(gemm_h, cudaFuncAttributeMaxDynamicSharedMemorySize, G_SMEM);

    PrepArgs pa;
    auto setj = [&](int i, const float* s, __half* d, int K, int R, int ih, int b0) {
        pa.j[i] = PrepJob{s, d, K, R, ih, b0};
    };
    setj(0, Wq_s, w_qkv_s,          1024, 1024, 1, 0);
    setj(1, Wk_s, w_qkv_s + MM,     1024, 1024, 1, 1024);
    setj(2, Wv_s, w_qkv_s + 2 * MM, 1024, 1024, 1, 2048);
    setj(3, Wo_s, w_o_s,            1024, 1024, 0, 3072);
    setj(4, Wq_c, w_qkv_c,          1024, 1024, 1, 4096);
    setj(5, Wk_c, w_qkv_c + MM,     1024, 1024, 1, 5120);
    setj(6, Wv_c, w_qkv_c + 2 * MM, 1024, 1024, 1, 6144);
    setj(7, Wo_c, w_o_c,            1024, 1024, 0, 7168);
    setj(8, W1,   w_1,              1024, 4096, 0, 8192);
    setj(9, W2,   w_2,              4096, 1024, 0, 12288);
    pa.dec = dec; pa.enc = enc; pa.dec_h = dec_h; pa.enc_h = enc_h;
    pa.b0 = bq_s; pa.b1 = bk_s; pa.b2 = bv_s;
    pa.b3 = bq_c; pa.b4 = bk_c; pa.b5 = bv_c;
    pa.o_self = biasQ; pa.o_cross = biasC;

    const dim3 gD (D_MODEL / 128, MROWS / 128);        // (8, 32)
    const dim3 gD3(3 * D_MODEL / 128, MROWS / 128);    // (24, 32)
    const dim3 gF (D_FF / 128,   MROWS / 128);         // (32, 32)
    const dim3 gA(TT / 128, N_HEADS, BB);

    mega_prep<<<PREP_TOTAL, 256>>>(pa);

    // ---- self-attention block ----
    gemm_h<<<gD3, 256, G_SMEM>>>(MROWS, 3 * D_MODEL, D_MODEL, dec_h, w_qkv_s,
                                 biasQ, QKV, 0, 1, nullptr, nullptr, 0, 0);
    attn_mma<true><<<gA, 256>>>(QKV, QKV + 1024, QKV + 2048, Ath, TT, 3072, 3072);
    gemm_h<<<gD, 256, G_SMEM>>>(MROWS, D_MODEL, D_MODEL, Ath, w_o_s, bo_s, Tm,
                                0, 0, nullptr, nullptr, 0, 0);
    add_ln_kernel<<<MROWS, 256>>>(dec, Tm, g1, be1, X1, Xh);

    // ---- cross-attention block: fused Q + KV projection (one launch) ----
    gemm_h<<<gD3, 256, G_SMEM>>>(MROWS, D_MODEL, D_MODEL, Xh, w_qkv_c,
                                 biasC, Qhc, 0, 1, enc_h, KVc, 1024, 2048);
    attn_mma<false><<<gA, 256>>>(Qhc, KVc, KVc + 1024, Ath, TT, 1024, 2048);
    gemm_h<<<gD, 256, G_SMEM>>>(MROWS, D_MODEL, D_MODEL, Ath, w_o_c, bo_c, Tm,
                                0, 0, nullptr, nullptr, 0, 0);
    add_ln_kernel<<<MROWS, 256>>>(X1, Tm, g2, be2, X2, Xh);

    // ---- FFN block ----
    gemm_h<<<gF, 256, G_SMEM>>>(MROWS, D_FF, D_MODEL, Xh, w_1, b1, Ffh,
                                1, 1, nullptr, nullptr, 0, 0);
    gemm_h<<<gD, 256, G_SMEM>>>(MROWS, D_MODEL, D_FF, Ffh, w_2, b2, Tm,
                                0, 0, nullptr, nullptr, 0, 0);
    add_ln_kernel<<<MROWS, 256>>>(X2, Tm, g3, be3, (float*)d_out, (__half*)nullptr);
}

// round 17
// speedup vs baseline: 1.0107x; 1.0009x over previous
#include <cuda_runtime.h>
#include <cuda_bf16.h>
#include <cuda_fp16.h>
#include <cstdint>
#include <cstddef>
#include <math.h>

#define D_MODEL 1024
#define N_HEADS 16
#define DKH     64
#define D_FF    4096
#define BB      2
#define TT      2048
#define MROWS   (BB * TT)   // 4096

__device__ float  g_Q   [MROWS * D_MODEL];
__device__ float  g_K   [MROWS * D_MODEL];
__device__ float  g_V   [MROWS * D_MODEL];
__device__ float  g_attn[MROWS * D_MODEL];
__device__ float  g_x1  [MROWS * D_MODEL];
__device__ float  g_x2  [MROWS * D_MODEL];
__device__ float  g_tmp [MROWS * D_MODEL];
__device__ float  g_ffn [MROWS * D_FF];
__device__ float  g_Wt  [D_FF * D_MODEL];          // holds Xh (fp16) + spare
__device__ __half g_wh  [16 * 1024 * 1024];        // 32MB: all transposed weights

// ======================= helpers ============================================
__device__ __forceinline__ uint32_t h2_as_u32(__half2 h) {
    union { __half2 h; uint32_t u; } cvt;
    cvt.h = h;
    return cvt.u;
}

__device__ __forceinline__ void cpa16(uint32_t dst, const void* src) {
    asm volatile("cp.async.cg.shared.global [%0], [%1], 16;\n"
                 :: "r"(dst), "l"(src) : "memory");
}
#define CP_COMMIT() asm volatile("cp.async.commit_group;\n" ::: "memory")
#define CP_WAIT(n)  asm volatile("cp.async.wait_group %0;\n" :: "n"(n) : "memory")

__device__ __forceinline__ uint32_t smem_u32(const void* p) {
    uint32_t a;
    asm("{ .reg .u64 t; cvta.to.shared.u64 t, %1; cvt.u32.u64 %0, t; }"
        : "=r"(a) : "l"(p));
    return a;
}

__device__ __forceinline__ void mma16h(float* c, uint32_t a0, uint32_t a1,
                                       uint32_t a2, uint32_t a3,
                                       uint32_t b0, uint32_t b1) {
    asm volatile(
        "mma.sync.aligned.m16n8k16.row.col.f32.f16.f16.f32 "
        "{%0,%1,%2,%3}, {%4,%5,%6,%7}, {%8,%9}, {%0,%1,%2,%3};"
        : "+f"(c[0]), "+f"(c[1]), "+f"(c[2]), "+f"(c[3])
        : "r"(a0), "r"(a1), "r"(a2), "r"(a3), "r"(b0), "r"(b1));
}

__device__ __forceinline__ void lsm4(uint32_t* r, uint32_t addr) {
    asm volatile("ldmatrix.sync.aligned.m8n8.x4.shared.b16 {%0,%1,%2,%3}, [%4];"
                 : "=r"(r[0]), "=r"(r[1]), "=r"(r[2]), "=r"(r[3]) : "r"(addr));
}

// =============== fp16 mma GEMM: C = A[M,K] @ Wt^T + bias ====================
// Block tile 128x128, 256 thr (8 warps, warp tile 32x64), BK = 64 halves.
// B fragments double-buffered across the n-tile loop (latency overlap).
// SPLIT2 variant: CTAs with bCol >= split read A2 and write C2 (ld2).
#define G_ROWB   144
#define G_STAGEB (256 * G_ROWB)            // 36864
#define G_BOFF   (128 * G_ROWB)            // 18432
#define G_NSTG   3
#define G_SMEM   (G_NSTG * G_STAGEB)       // 110592

template<int SPLIT2>
__global__ __launch_bounds__(256, 2)
void gemm_h(int M, int N, int K,
            const __half* __restrict__ A, const __half* __restrict__ Wt,
            const float* __restrict__ bias, void* __restrict__ C,
            int relu, int outHalf,
            const __half* __restrict__ A2, __half* __restrict__ C2,
            int split, int ld2)
{
    extern __shared__ char smc[];
    const uint32_t sb = smem_u32(smc);

    const int tid = threadIdx.x;
    const int wid = tid >> 5, lid = tid & 31;
    const int g = lid >> 2, tg = lid & 3;
    const int wm = wid >> 1, wn = wid & 1;

    const int bRow = blockIdx.y * 128, bCol = blockIdx.x * 128;
    const int NT = K >> 6;
    const bool reg2 = SPLIT2 && (bCol >= split);
    const __half* Asel = reg2 ? A2 : A;

    float acc[2][8][4];
#pragma unroll
    for (int m = 0; m < 2; m++)
#pragma unroll
        for (int n = 0; n < 8; n++)
#pragma unroll
            for (int x = 0; x < 4; x++) acc[m][n][x] = 0.f;

    auto load_stage = [&](int it, int s) {
        const uint32_t base = sb + s * G_STAGEB;
#pragma unroll
        for (int j = 0; j < 4; j++) {
            const int idx = tid + 256 * j;
            const int row = idx >> 3, c16 = idx & 7;
            cpa16(base + row * G_ROWB + c16 * 16,
                  Asel + (size_t)(bRow + row) * K + it * 64 + c16 * 8);
        }
#pragma unroll
        for (int j = 0; j < 4; j++) {
            const int idx = tid + 256 * j;
            const int row = idx >> 3, c16 = idx & 7;
            cpa16(base + G_BOFF + row * G_ROWB + c16 * 16,
                  Wt + (size_t)(bCol + row) * K + it * 64 + c16 * 8);
        }
    };

    const uint32_t aoff = (uint32_t)((wm * 32 + (lid & 7) + ((lid >> 3) & 1) * 8) * G_ROWB
                                     + (lid >> 4) * 16);
    const uint32_t boff = (uint32_t)(G_BOFF
                                     + (wn * 64 + (lid & 7) + (lid >> 4) * 8) * G_ROWB
                                     + ((lid >> 3) & 1) * 16);

    load_stage(0, 0); CP_COMMIT();
    load_stage(1, 1); CP_COMMIT();

    for (int i = 0; i < NT; i++) {
        CP_WAIT(1);
        __syncthreads();
        const int pre = i + 2;
        if (pre < NT) load_stage(pre, pre % G_NSTG);
        CP_COMMIT();

        const uint32_t buf = sb + (i % G_NSTG) * G_STAGEB;
#pragma unroll
        for (int ks = 0; ks < 4; ks++) {
            uint32_t a[2][4];
#pragma unroll
            for (int mt = 0; mt < 2; mt++)
                lsm4(a[mt], buf + aoff + mt * 16 * G_ROWB + ks * 32);
            uint32_t b[2][4];
            lsm4(b[0], buf + boff + ks * 32);      // prefetch p=0
#pragma unroll
            for (int p = 0; p < 4; p++) {
                if (p < 3)
                    lsm4(b[(p + 1) & 1], buf + boff + (p + 1) * 16 * G_ROWB + ks * 32);
                const uint32_t* bp = b[p & 1];
#pragma unroll
                for (int mt = 0; mt < 2; mt++) {
                    mma16h(acc[mt][2 * p],     a[mt][0], a[mt][1], a[mt][2],
                           a[mt][3], bp[0], bp[1]);
                    mma16h(acc[mt][2 * p + 1], a[mt][0], a[mt][1], a[mt][2],
                           a[mt][3], bp[2], bp[3]);
                }
            }
        }
    }

    float* Cf = (float*)C;
    __half* Ch = reg2 ? C2 : (__half*)C;
    const int ldo = reg2 ? ld2 : N;
    const int cbase = reg2 ? (bCol - split) : bCol;
#pragma unroll
    for (int mt = 0; mt < 2; mt++) {
        const int r0 = bRow + wm * 32 + mt * 16 + g;
#pragma unroll
        for (int nt = 0; nt < 8; nt++) {
            const int gcol = bCol + wn * 64 + nt * 8 + 2 * tg;       // bias index
            const int col  = cbase + wn * 64 + nt * 8 + 2 * tg;      // output index
            const float bi0 = bias[gcol], bi1 = bias[gcol + 1];
            float v0 = acc[mt][nt][0] + bi0, v1 = acc[mt][nt][1] + bi1;
            float v2 = acc[mt][nt][2] + bi0, v3 = acc[mt][nt][3] + bi1;
            if (relu) {
                v0 = fmaxf(v0, 0.f); v1 = fmaxf(v1, 0.f);
                v2 = fmaxf(v2, 0.f); v3 = fmaxf(v3, 0.f);
            }
            if (outHalf || reg2) {
                *(__half2*)(Ch + (size_t)r0 * ldo + col) = __floats2half2_rn(v0, v1);
                *(__half2*)(Ch + (size_t)(r0 + 8) * ldo + col) = __floats2half2_rn(v2, v3);
            } else {
                *(float2*)(Cf + (size_t)r0 * ldo + col) = make_float2(v0, v1);
                *(float2*)(Cf + (size_t)(r0 + 8) * ldo + col) = make_float2(v2, v3);
            }
        }
    }
}

// ---------------- mega prep: weights + activations + biases, ONE launch -----
struct PrepJob { const float* src; __half* dst; int K, R, isHead, blk0; };
struct PrepArgs {
    PrepJob j[10];
    const float *dec, *enc;
    __half *dec_h, *enc_h;
    const float *b0, *b1, *b2, *b3, *b4, *b5;   // bq_s bk_s bv_s bq_c bk_c bv_c
    float *o_self, *o_cross;                    // 3072 each
};

#define PREP_WBLK  16384
#define PREP_DEC   (PREP_WBLK)          // 4096 blocks
#define PREP_ENC   (PREP_DEC + 4096)
#define PREP_BIAS  (PREP_ENC + 4096)    // 24 blocks
#define PREP_TOTAL (PREP_BIAS + 24)

__global__ __launch_bounds__(256) void mega_prep(PrepArgs pa)
{
    __shared__ float t[32][33];
    const int bx = blockIdx.x, tid = threadIdx.x;

    if (bx < PREP_WBLK) {
        int ji = 0;
#pragma unroll
        for (int q = 1; q < 10; q++)
            if (bx >= pa.j[q].blk0) ji = q;
        const PrepJob& J = pa.j[ji];
        const int b = bx - J.blk0;
        const int kt = J.K >> 5;
        const int kx = b % kt, rx = b / kt;
        const int k0 = kx * 32, r0 = rx * 32;
        const int x = tid & 31, y = tid >> 5;

        if (J.isHead) {
#pragma unroll
            for (int jj = 0; jj < 32; jj += 8) {
                const int n = r0 + x;
                const int hh = n >> 6, d = n & 63;
                t[y + jj][x] = J.src[((size_t)hh * J.K + (k0 + y + jj)) * 64 + d];
            }
        } else {
#pragma unroll
            for (int jj = 0; jj < 32; jj += 8)
                t[y + jj][x] = J.src[(size_t)(k0 + y + jj) * J.R + r0 + x];
        }
        __syncthreads();
#pragma unroll
        for (int jj = 0; jj < 32; jj += 8)
            J.dst[(size_t)(r0 + y + jj) * J.K + k0 + x] = __float2half_rn(t[x][y + jj]);
    } else if (bx < PREP_ENC) {
        const int i = (bx - PREP_DEC) * 256 + tid;
        float4 v = ((const float4*)pa.dec)[i];
        uint2 o;
        o.x = h2_as_u32(__floats2half2_rn(v.x, v.y));
        o.y = h2_as_u32(__floats2half2_rn(v.z, v.w));
        ((uint2*)pa.dec_h)[i] = o;
    } else if (bx < PREP_BIAS) {
        const int i = (bx - PREP_ENC) * 256 + tid;
        float4 v = ((const float4*)pa.enc)[i];
        uint2 o;
        o.x = h2_as_u32(__floats2half2_rn(v.x, v.y));
        o.y = h2_as_u32(__floats2half2_rn(v.z, v.w));
        ((uint2*)pa.enc_h)[i] = o;
    } else {
        const int i = (bx - PREP_BIAS) * 256 + tid;    // 0..6143
        if (i < 1024)      pa.o_self[i] = pa.b0[i];
        else if (i < 2048) pa.o_self[i] = pa.b1[i - 1024];
        else if (i < 3072) pa.o_self[i] = pa.b2[i - 2048];
        else if (i < 4096) pa.o_cross[i - 3072] = pa.b3[i - 3072];
        else if (i < 5120) pa.o_cross[i - 3072] = pa.b4[i - 4096];
        else               pa.o_cross[i - 3072] = pa.b5[i - 5120];
    }
}

// ========== flash attention: 128-query blocks, 256 thr, fp16 mma ============
#define AROW 36   // b32 words per smem row (72 halves)

template<bool CAUSAL>
__global__ __launch_bounds__(256) void attn_mma(
    const __half* __restrict__ Q, const __half* __restrict__ K,
    const __half* __restrict__ V, __half* __restrict__ O,
    int T, int ldq, int ldkv)
{
    __shared__ __align__(16) __half Qs[128 * 72];
    __shared__ __align__(16) __half Ks[64 * 72];
    __shared__ __align__(16) __half Vt[64 * 72];

    const int tid = threadIdx.x, wid = tid >> 5, lid = tid & 31;
    const int g = lid >> 2, tg = lid & 3;
    const int h = blockIdx.y, b = blockIdx.z;
    const int bx = CAUSAL ? (gridDim.x - 1 - blockIdx.x) : blockIdx.x;
    const int q0 = bx * 128;
    const size_t qbase  = (size_t)b * T * ldq  + h * DKH;
    const size_t kvbase = (size_t)b * T * ldkv + h * DKH;
    const size_t obase  = (size_t)b * T * D_MODEL + h * DKH;

    const int fr0 = tid >> 3, fc = (tid & 7) * 8;
    const int fr1 = fr0 + 32;

    for (int idx = tid; idx < 128 * 8; idx += 256) {
        const int r = idx >> 3, c8 = idx & 7;
        *(uint4*)&Qs[r * 72 + c8 * 8] =
            *(const uint4*)(Q + qbase + (size_t)(q0 + r) * ldq + c8 * 8);
    }
    __syncthreads();

    uint32_t qf[4][4];
    {
        const uint32_t* Qu = (const uint32_t*)Qs;
        const int r0 = wid * 16 + g;
#pragma unroll
        for (int kc = 0; kc < 4; kc++) {
            const int c = 8 * kc + tg;
            qf[kc][0] = Qu[r0 * AROW + c];
            qf[kc][1] = Qu[(r0 + 8) * AROW + c];
            qf[kc][2] = Qu[r0 * AROW + c + 4];
            qf[kc][3] = Qu[(r0 + 8) * AROW + c + 4];
        }
    }

    float oacc[8][4];
#pragma unroll
    for (int j = 0; j < 8; j++)
#pragma unroll
        for (int x = 0; x < 4; x++) oacc[j][x] = 0.f;
    float m0 = -1e30f, m1 = -1e30f, l0 = 0.f, l1 = 0.f;

    const int nkt = CAUSAL ? 2 * (bx + 1) : (T / 64);

    uint4 kreg0, kreg1, vreg0, vreg1;
    {
        const size_t a0 = kvbase + (size_t)fr0 * ldkv + fc;
        const size_t a1 = kvbase + (size_t)fr1 * ldkv + fc;
        kreg0 = *(const uint4*)(K + a0); vreg0 = *(const uint4*)(V + a0);
        kreg1 = *(const uint4*)(K + a1); vreg1 = *(const uint4*)(V + a1);
    }

    for (int kt = 0; kt < nkt; kt++) {
        const int s0 = kt * 64;
        __syncthreads();
        *(uint4*)&Ks[fr0 * 72 + fc] = kreg0;
        *(uint4*)&Ks[fr1 * 72 + fc] = kreg1;
        {
            const __half* hv = (const __half*)&vreg0;
#pragma unroll
            for (int q = 0; q < 8; q++) Vt[(fc + q) * 72 + fr0] = hv[q];
            hv = (const __half*)&vreg1;
#pragma unroll
            for (int q = 0; q < 8; q++) Vt[(fc + q) * 72 + fr1] = hv[q];
        }
        if (kt + 1 < nkt) {
            const size_t a0 = kvbase + (size_t)(s0 + 64 + fr0) * ldkv + fc;
            const size_t a1 = kvbase + (size_t)(s0 + 64 + fr1) * ldkv + fc;
            kreg0 = *(const uint4*)(K + a0); vreg0 = *(const uint4*)(V + a0);
            kreg1 = *(const uint4*)(K + a1); vreg1 = *(const uint4*)(V + a1);
        }
        __syncthreads();

        if (CAUSAL && s0 >= q0 + wid * 16 + 16) continue;

        float sacc[8][4];
#pragma unroll
        for (int j = 0; j < 8; j++)
#pragma unroll
            for (int x = 0; x < 4; x++) sacc[j][x] = 0.f;
        {
            const uint32_t* Ku = (const uint32_t*)Ks;
#pragma unroll
            for (int j = 0; j < 8; j++) {
                const int rb = (8 * j + g) * AROW + tg;
#pragma unroll
                for (int kc = 0; kc < 4; kc++) {
                    const uint32_t b0 = Ku[rb + 8 * kc];
                    const uint32_t b1 = Ku[rb + 8 * kc + 4];
                    mma16h(sacc[j], qf[kc][0], qf[kc][1], qf[kc][2], qf[kc][3],
                           b0, b1);
                }
            }
        }
#pragma unroll
        for (int j = 0; j < 8; j++) {
            sacc[j][0] *= 0.125f; sacc[j][1] *= 0.125f;
            sacc[j][2] *= 0.125f; sacc[j][3] *= 0.125f;
        }

        if (CAUSAL && s0 + 63 >= q0 + wid * 16) {
            const int r0 = q0 + wid * 16 + g, r1 = r0 + 8;
#pragma unroll
            for (int j = 0; j < 8; j++) {
                const int c0 = s0 + 8 * j + 2 * tg, c1 = c0 + 1;
                if (c0 > r0) sacc[j][0] = -INFINITY;
                if (c1 > r0) sacc[j][1] = -INFINITY;
                if (c0 > r1) sacc[j][2] = -INFINITY;
                if (c1 > r1) sacc[j][3] = -INFINITY;
            }
        }

        float tm0 = -1e30f, tm1 = -1e30f;
#pragma unroll
        for (int j = 0; j < 8; j++) {
            tm0 = fmaxf(tm0, fmaxf(sacc[j][0], sacc[j][1]));
            tm1 = fmaxf(tm1, fmaxf(sacc[j][2], sacc[j][3]));
        }
        tm0 = fmaxf(tm0, __shfl_xor_sync(0xffffffffu, tm0, 1));
        tm0 = fmaxf(tm0, __shfl_xor_sync(0xffffffffu, tm0, 2));
        tm1 = fmaxf(tm1, __shfl_xor_sync(0xffffffffu, tm1, 1));
        tm1 = fmaxf(tm1, __shfl_xor_sync(0xffffffffu, tm1, 2));

        const float mn0 = fmaxf(m0, tm0), mn1 = fmaxf(m1, tm1);
        const float cr0 = __expf(m0 - mn0), cr1 = __expf(m1 - mn1);
        m0 = mn0; m1 = mn1;

        uint32_t ph[8][2];
        float ts0 = 0.f, ts1 = 0.f;
#pragma unroll
        for (int j = 0; j < 8; j++) {
            const float p0 = __expf(sacc[j][0] - mn0);
            const float p1 = __expf(sacc[j][1] - mn0);
            const float p2 = __expf(sacc[j][2] - mn1);
            const float p3 = __expf(sacc[j][3] - mn1);
            ts0 += p0 + p1; ts1 += p2 + p3;
            ph[j][0] = h2_as_u32(__floats2half2_rn(p0, p1));
            ph[j][1] = h2_as_u32(__floats2half2_rn(p2, p3));
        }
        ts0 += __shfl_xor_sync(0xffffffffu, ts0, 1);
        ts0 += __shfl_xor_sync(0xffffffffu, ts0, 2);
        ts1 += __shfl_xor_sync(0xffffffffu, ts1, 1);
        ts1 += __shfl_xor_sync(0xffffffffu, ts1, 2);
        l0 = l0 * cr0 + ts0;
        l1 = l1 * cr1 + ts1;

#pragma unroll
        for (int j = 0; j < 8; j++) {
            oacc[j][0] *= cr0; oacc[j][1] *= cr0;
            oacc[j][2] *= cr1; oacc[j][3] *= cr1;
        }

        {
            const uint32_t* Vu = (const uint32_t*)Vt;
#pragma unroll
            for (int j = 0; j < 8; j++) {
                const int rb = (8 * j + g) * AROW + tg;
#pragma unroll
                for (int kc = 0; kc < 4; kc++) {
                    const uint32_t b0 = Vu[rb + 8 * kc];
                    const uint32_t b1 = Vu[rb + 8 * kc + 4];
                    mma16h(oacc[j], ph[2 * kc][0], ph[2 * kc][1],
                           ph[2 * kc + 1][0], ph[2 * kc + 1][1], b0, b1);
                }
            }
        }
    }

    const float inv0 = 1.f / l0, inv1 = 1.f / l1;
    const int r0 = q0 + wid * 16 + g;
#pragma unroll
    for (int j = 0; j < 8; j++) {
        const int col = 8 * j + 2 * tg;
        *(__half2*)(O + obase + (size_t)r0 * D_MODEL + col) =
            __floats2half2_rn(oacc[j][0] * inv0, oacc[j][1] * inv0);
        *(__half2*)(O + obase + (size_t)(r0 + 8) * D_MODEL + col) =
            __floats2half2_rn(oacc[j][2] * inv1, oacc[j][3] * inv1);
    }
}

// ---------------- residual add + LayerNorm ----------------------------------
__inline__ __device__ float warpSum(float v) {
#pragma unroll
    for (int o = 16; o > 0; o >>= 1) v += __shfl_xor_sync(0xffffffffu, v, o);
    return v;
}

__global__ __launch_bounds__(256) void add_ln_kernel(
    const float* __restrict__ res, const float* __restrict__ y,
    const float* __restrict__ gamma, const float* __restrict__ beta,
    float* __restrict__ out, __half* __restrict__ outh)
{
    const int row = blockIdx.x;
    const int i = threadIdx.x;
    const float4 a  = ((const float4*)(res + (size_t)row * D_MODEL))[i];
    const float4 b4 = ((const float4*)(y   + (size_t)row * D_MODEL))[i];
    const float x0 = a.x + b4.x, x1 = a.y + b4.y, x2 = a.z + b4.z, x3 = a.w + b4.w;

    float s  = x0 + x1 + x2 + x3;
    float sq = x0 * x0 + x1 * x1 + x2 * x2 + x3 * x3;
    s = warpSum(s); sq = warpSum(sq);

    __shared__ float sh[2][8];
    const int w = threadIdx.x >> 5, l = threadIdx.x & 31;
    if (l == 0) { sh[0][w] = s; sh[1][w] = sq; }
    __syncthreads();
    if (threadIdx.x < 32) {
        float aa = (l < 8) ? sh[0][l] : 0.f;
        float bb = (l < 8) ? sh[1][l] : 0.f;
        aa = warpSum(aa); bb = warpSum(bb);
        if (l == 0) { sh[0][0] = aa; sh[1][0] = bb; }
    }
    __syncthreads();
    const float mean = sh[0][0] * (1.f / D_MODEL);
    const float var  = sh[1][0] * (1.f / D_MODEL) - mean * mean;
    const float rinv = rsqrtf(var + 1e-5f);

    const float4 gm = ((const float4*)gamma)[i];
    const float4 be = ((const float4*)beta)[i];
    float4 o;
    o.x = (x0 - mean) * rinv * gm.x + be.x;
    o.y = (x1 - mean) * rinv * gm.y + be.y;
    o.z = (x2 - mean) * rinv * gm.z + be.z;
    o.w = (x3 - mean) * rinv * gm.w + be.w;
    ((float4*)(out + (size_t)row * D_MODEL))[i] = o;
    if (outh) {
        uint2 oh;
        oh.x = h2_as_u32(__floats2half2_rn(o.x, o.y));
        oh.y = h2_as_u32(__floats2half2_rn(o.z, o.w));
        ((uint2*)(outh + (size_t)row * D_MODEL))[i] = oh;
    }
}

// ---------------- launch ----------------------------------------------------
extern "C" void kernel_launch(void* const* d_in, const int* in_sizes, int n_in,
                              void* d_out, int out_size)
{
    const float* dec  = (const float*)d_in[0];
    const float* enc  = (const float*)d_in[1];
    const float* Wq_s = (const float*)d_in[2];
    const float* bq_s = (const float*)d_in[3];
    const float* Wk_s = (const float*)d_in[4];
    const float* bk_s = (const float*)d_in[5];
    const float* Wv_s = (const float*)d_in[6];
    const float* bv_s = (const float*)d_in[7];
    const float* Wo_s = (const float*)d_in[8];
    const float* bo_s = (const float*)d_in[9];
    const float* Wq_c = (const float*)d_in[10];
    const float* bq_c = (const float*)d_in[11];
    const float* Wk_c = (const float*)d_in[12];
    const float* bk_c = (const float*)d_in[13];
    const float* Wv_c = (const float*)d_in[14];
    const float* bv_c = (const float*)d_in[15];
    const float* Wo_c = (const float*)d_in[16];
    const float* bo_c = (const float*)d_in[17];
    const float* W1   = (const float*)d_in[18];
    const float* b1   = (const float*)d_in[19];
    const float* W2   = (const float*)d_in[20];
    const float* b2   = (const float*)d_in[21];
    const float* g1   = (const float*)d_in[22];
    const float* be1  = (const float*)d_in[23];
    const float* g2   = (const float*)d_in[24];
    const float* be2  = (const float*)d_in[25];
    const float* g3   = (const float*)d_in[26];
    const float* be3  = (const float*)d_in[27];

    float *Qf, *Kf, *Vf, *Af, *X1, *X2, *Tm, *Fbuf, *Wtb;
    __half* Wh;
    cudaGetSymbolAddress((void**)&Qf, g_Q);
    cudaGetSymbolAddress((void**)&Kf, g_K);
    cudaGetSymbolAddress((void**)&Vf, g_V);
    cudaGetSymbolAddress((void**)&Af, g_attn);
    cudaGetSymbolAddress((void**)&X1, g_x1);
    cudaGetSymbolAddress((void**)&X2, g_x2);
    cudaGetSymbolAddress((void**)&Tm, g_tmp);
    cudaGetSymbolAddress((void**)&Fbuf, g_ffn);
    cudaGetSymbolAddress((void**)&Wtb, g_Wt);
    cudaGetSymbolAddress((void**)&Wh, g_wh);

    const size_t NE = (size_t)MROWS * D_MODEL;        // 4M
    const size_t MM = (size_t)D_MODEL * D_MODEL;      // 1M
    __half* dec_h = (__half*)Qf;
    __half* enc_h = dec_h + NE;
    __half* Qhc   = (__half*)Kf;
    __half* KVc   = (__half*)Vf;                      // ld 2048
    __half* Ath   = (__half*)Af;
    float*  biasQ = (float*)(Ath + NE);               // self 3072
    float*  biasC = biasQ + 4096;                     // cross 3072
    __half* QKV   = (__half*)Fbuf;                    // ld 3072
    __half* Ffh   = QKV + (size_t)MROWS * 3072;
    __half* w_qkv_s = Wh;
    __half* w_o_s   = Wh + 3 * MM;
    __half* w_qkv_c = Wh + 4 * MM;
    __half* w_o_c   = Wh + 7 * MM;
    __half* w_1     = Wh + 8 * MM;
    __half* w_2     = Wh + 12 * MM;
    __half* Xh      = (__half*)Wtb;

    cudaFuncSetAttribute(gemm_h<0>, cudaFuncAttributeMaxDynamicSharedMemorySize, G_SMEM);
    cudaFuncSetAttribute(gemm_h<1>, cudaFuncAttributeMaxDynamicSharedMemorySize, G_SMEM);

    PrepArgs pa;
    auto setj = [&](int i, const float* s, __half* d, int K, int R, int ih, int b0) {
        pa.j[i] = PrepJob{s, d, K, R, ih, b0};
    };
    setj(0, Wq_s, w_qkv_s,          1024, 1024, 1, 0);
    setj(1, Wk_s, w_qkv_s + MM,     1024, 1024, 1, 1024);
    setj(2, Wv_s, w_qkv_s + 2 * MM, 1024, 1024, 1, 2048);
    setj(3, Wo_s, w_o_s,            1024, 1024, 0, 3072);
    setj(4, Wq_c, w_qkv_c,          1024, 1024, 1, 4096);
    setj(5, Wk_c, w_qkv_c + MM,     1024, 1024, 1, 5120);
    setj(6, Wv_c, w_qkv_c + 2 * MM, 1024, 1024, 1, 6144);
    setj(7, Wo_c, w_o_c,            1024, 1024, 0, 7168);
    setj(8, W1,   w_1,              1024, 4096, 0, 8192);
    setj(9, W2,   w_2,              4096, 1024, 0, 12288);
    pa.dec = dec; pa.enc = enc; pa.dec_h = dec_h; pa.enc_h = enc_h;
    pa.b0 = bq_s; pa.b1 = bk_s; pa.b2 = bv_s;
    pa.b3 = bq_c; pa.b4 = bk_c; pa.b5 = bv_c;
    pa.o_self = biasQ; pa.o_cross = biasC;

    const dim3 gD (D_MODEL / 128, MROWS / 128);        // (8, 32)
    const dim3 gD3(3 * D_MODEL / 128, MROWS / 128);    // (24, 32)
    const dim3 gF (D_FF / 128,   MROWS / 128);         // (32, 32)
    const dim3 gA(TT / 128, N_HEADS, BB);

    mega_prep<<<PREP_TOTAL, 256>>>(pa);

    // ---- self-attention block ----
    gemm_h<0><<<gD3, 256, G_SMEM>>>(MROWS, 3 * D_MODEL, D_MODEL, dec_h, w_qkv_s,
                                    biasQ, QKV, 0, 1, nullptr, nullptr, 0, 0);
    attn_mma<true><<<gA, 256>>>(QKV, QKV + 1024, QKV + 2048, Ath, TT, 3072, 3072);
    gemm_h<0><<<gD, 256, G_SMEM>>>(MROWS, D_MODEL, D_MODEL, Ath, w_o_s, bo_s, Tm,
                                   0, 0, nullptr, nullptr, 0, 0);
    add_ln_kernel<<<MROWS, 256>>>(dec, Tm, g1, be1, X1, Xh);

    // ---- cross-attention block: fused Q + KV projection (one launch) ----
    gemm_h<1><<<gD3, 256, G_SMEM>>>(MROWS, D_MODEL, D_MODEL, Xh, w_qkv_c,
                                    biasC, Qhc, 0, 1, enc_h, KVc, 1024, 2048);
    attn_mma<false><<<gA, 256>>>(Qhc, KVc, KVc + 1024, Ath, TT, 1024, 2048);
    gemm_h<0><<<gD, 256, G_SMEM>>>(MROWS, D_MODEL, D_MODEL, Ath, w_o_c, bo_c, Tm,
                                   0, 0, nullptr, nullptr, 0, 0);
    add_ln_kernel<<<MROWS, 256>>>(X1, Tm, g2, be2, X2, Xh);

    // ---- FFN block ----
    gemm_h<0><<<gF, 256, G_SMEM>>>(MROWS, D_FF, D_MODEL, Xh, w_1, b1, Ffh,
                                   1, 1, nullptr, nullptr, 0, 0);
    gemm_h<0><<<gD, 256, G_SMEM>>>(MROWS, D_MODEL, D_FF, Ffh, w_2, b2, Tm,
                                   0, 0, nullptr, nullptr, 0, 0);
    add_ln_kernel<<<MROWS, 256>>>(X2, Tm, g3, be3, (float*)d_out, (__half*)nullptr);
}